// round 8
// baseline (speedup 1.0000x reference)
#include <cuda_runtime.h>

// y = x*2 + 5 - 3/(1+x), elementwise over 8192*8192 fp32 (64M elems).
// R8: persistent grid-stride kernel — exactly one wave (148 SMs x 6 CTAs),
// each CTA loops over the array so the per-SM load pipeline never drains at
// CTA boundaries. V=4 float4 front-batched per iteration, streaming hints,
// fast reciprocal.

constexpr int V = 4;    // float4 per iteration per thread
constexpr int T = 256;  // threads per block
constexpr int GRID = 148 * 6;  // one wave at ~6 CTAs/SM (regs ~32)

__global__ __launch_bounds__(T)
void elementwise_persist_kernel(const float4* __restrict__ in,
                                float4* __restrict__ out,
                                int n4) {
    const int stride = GRID * T * V;   // float4s per full-grid iteration
    int base = blockIdx.x * (T * V) + threadIdx.x;

    for (; base + (V - 1) * T < n4; base += stride) {
        float4 v[V];
#pragma unroll
        for (int k = 0; k < V; k++) {
            v[k] = __ldcs(&in[base + k * T]);   // front-batched LDG.E.128
        }
#pragma unroll
        for (int k = 0; k < V; k++) {
            float4 r;
            r.x = fmaf(v[k].x, 2.0f, 5.0f) - __fdividef(3.0f, 1.0f + v[k].x);
            r.y = fmaf(v[k].y, 2.0f, 5.0f) - __fdividef(3.0f, 1.0f + v[k].y);
            r.z = fmaf(v[k].z, 2.0f, 5.0f) - __fdividef(3.0f, 1.0f + v[k].z);
            r.w = fmaf(v[k].w, 2.0f, 5.0f) - __fdividef(3.0f, 1.0f + v[k].w);
            __stcs(&out[base + k * T], r);
        }
    }
    // n4 = 16777216 is not an exact multiple of stride (909312); handle tail
    // elements (scalar-chunk remainder) with a guarded pass.
    for (; base < n4; base += stride) {
#pragma unroll
        for (int k = 0; k < V; k++) {
            int idx = base + k * T;
            if (idx < n4) {
                float4 x = __ldcs(&in[idx]);
                float4 r;
                r.x = fmaf(x.x, 2.0f, 5.0f) - __fdividef(3.0f, 1.0f + x.x);
                r.y = fmaf(x.y, 2.0f, 5.0f) - __fdividef(3.0f, 1.0f + x.y);
                r.z = fmaf(x.z, 2.0f, 5.0f) - __fdividef(3.0f, 1.0f + x.z);
                r.w = fmaf(x.w, 2.0f, 5.0f) - __fdividef(3.0f, 1.0f + x.w);
                __stcs(&out[idx], r);
            }
        }
    }
}

extern "C" void kernel_launch(void* const* d_in, const int* in_sizes, int n_in,
                              void* d_out, int out_size) {
    const float* x = (const float*)d_in[0];
    float* y = (float*)d_out;
    int n = in_sizes[0];          // 67108864 = 8192*8192
    int n4 = n >> 2;              // 16777216 float4

    elementwise_persist_kernel<<<GRID, T>>>(
        (const float4*)x, (float4*)y, n4);
}

// round 9
// speedup vs baseline: 1.1300x; 1.1300x over previous
#include <cuda_runtime.h>

// y = x*2 + 5 - 3/(1+x), elementwise over 8192*8192 fp32 (64M elems).
// FINAL (locked): best measured configuration across 8 explored rounds.
//   - 4x float4 per thread, front-batched (MLP=4), 256-thread blocks,
//     16384-CTA oversubscribed grid (deep CTA pool keeps HBM queues full;
//     persistent single-wave variant measured 13% WORSE).
//   - streaming cache hints (ld/st.global.cs) on the pass-through data.
//   - __fdividef: MUFU.RCP+MUL (rel_err ~3e-8 << 1e-3 threshold).
// Pinned at the mixed read+write HBM3e wall: 6.44-6.50 TB/s measured across
// all request-supply / cache-policy / wave-structure variants.

constexpr int V = 4;    // float4 per thread
constexpr int T = 256;  // threads per block

__global__ __launch_bounds__(T)
void elementwise_final_kernel(const float4* __restrict__ in,
                              float4* __restrict__ out) {
    int base = blockIdx.x * (T * V) + threadIdx.x;

    float4 v[V];
#pragma unroll
    for (int k = 0; k < V; k++) {
        v[k] = __ldcs(&in[base + k * T]);   // 4 independent LDG.E.128, front-batched
    }

#pragma unroll
    for (int k = 0; k < V; k++) {
        float4 r;
        r.x = fmaf(v[k].x, 2.0f, 5.0f) - __fdividef(3.0f, 1.0f + v[k].x);
        r.y = fmaf(v[k].y, 2.0f, 5.0f) - __fdividef(3.0f, 1.0f + v[k].y);
        r.z = fmaf(v[k].z, 2.0f, 5.0f) - __fdividef(3.0f, 1.0f + v[k].z);
        r.w = fmaf(v[k].w, 2.0f, 5.0f) - __fdividef(3.0f, 1.0f + v[k].w);
        __stcs(&out[base + k * T], r);
    }
}

extern "C" void kernel_launch(void* const* d_in, const int* in_sizes, int n_in,
                              void* d_out, int out_size) {
    const float* x = (const float*)d_in[0];
    float* y = (float*)d_out;
    int n = in_sizes[0];          // 67108864 = 8192*8192
    int n4 = n >> 2;              // 16777216 float4

    // Exact tiling: 16777216 / (256*4) = 16384 blocks, no tail.
    int blocks = n4 / (T * V);
    elementwise_final_kernel<<<blocks, T>>>(
        (const float4*)x, (float4*)y);
}